// round 12
// baseline (speedup 1.0000x reference)
#include <cuda_runtime.h>
#include <cuda_fp16.h>

#define TW 182
#define RW 192
#define STRIP 256
#define CHUNKS 16
#define PITCH 772      // u32 words per pair-row; 772%32==4 -> conflict-free LDS.128
#define BUFWORDS (8 * PITCH)             // 6176
#define SMEM_WORDS (2 * BUFWORDS + 160)  // pad covers phase-C tail overreads
#define NTHREADS 192
#define IMG_W 512
#define IMG_H 512
#define PLANES 96
#define NBLOCKS (3 * 2 * 96)             // 576 = one full wave at 4 CTAs/SM
#define NPIX 25165824.0f

static constexpr float C1V = 0.0001f;
static constexpr float C2V = 0.0009f;

// fp16 bit patterns of the Gaussian(sigma=1.5,k=11) weights (== cvt.rn.f16.f32)
__host__ __device__ constexpr unsigned hw(int k) {
    return (k == 0 || k == 10) ? 0x1436u
         : (k == 1 || k == 9)  ? 0x1FC8u
         : (k == 2 || k == 8)  ? 0x289Cu
         : (k == 3 || k == 7)  ? 0x2F00u
         : (k == 4 || k == 6)  ? 0x32D1u
         : (k == 5)            ? 0x3442u
         : 0u;
}
// vertical weight pair (lo=w[k], hi=w[k-1]); horizontal broadcast
__host__ __device__ constexpr unsigned wk2(int k) { return hw(k) | (hw(k - 1) << 16); }
__host__ __device__ constexpr unsigned wb2(int k) { return hw(k) | (hw(k) << 16); }

__device__ float g_accum;
__device__ unsigned int g_count;

__device__ __forceinline__ unsigned hfma2u(unsigned a, unsigned b, unsigned c) {
    unsigned d; asm("fma.rn.f16x2 %0,%1,%2,%3;" : "=r"(d) : "r"(a), "r"(b), "r"(c)); return d;
}
__device__ __forceinline__ unsigned hmul2u(unsigned a, unsigned b) {
    unsigned d; asm("mul.rn.f16x2 %0,%1,%2;" : "=r"(d) : "r"(a), "r"(b)); return d;
}
__device__ __forceinline__ unsigned bcast_h2(float f) {
    unsigned d; asm("cvt.rn.f16x2.f32 %0, %1, %1;" : "=r"(d) : "f"(f)); return d;
}
__device__ __forceinline__ float2 unpack_h2(unsigned u) {
    __half2 h = *reinterpret_cast<__half2*>(&u);
    return make_float2(__low2float(h), __high2float(h));
}

// One vertical-pass input row: centered load + moments + taps into the ring.
// K = tap index of ring slot SL0-aligned stream; taps use compile-time k.
__device__ __forceinline__ void load_centered(const float* __restrict__ p1,
                                              const float* __restrict__ p2,
                                              int gy, int gx, bool xok,
                                              float& a, float& b) {
    a = -0.5f; b = -0.5f;
    const bool ok = xok && (gy >= 0) && (gy < IMG_H);
    if (ok) {
        const int idx = gy * IMG_W + gx;
        a = __ldg(p1 + idx) - 0.5f;
        b = __ldg(p2 + idx) - 0.5f;
    }
}

__device__ __forceinline__ void make_pq(float a, float b, unsigned (&pq)[4]) {
    pq[0] = bcast_h2(a);
    pq[1] = bcast_h2(b);
    pq[2] = hfma2u(pq[0], pq[0], hmul2u(pq[1], pq[1]));  // ac^2 + bc^2
    pq[3] = hmul2u(pq[0], pq[1]);                        // ac * bc
}

__global__ void __launch_bounds__(NTHREADS, 4)
ssim_main(const float* __restrict__ img1, const float* __restrict__ img2,
          float* __restrict__ out) {
    extern __shared__ unsigned vw[];      // [2][8][PITCH] + pad
    __shared__ float red[NTHREADS / 32];

    const int tx = threadIdx.x;
    const int plane = blockIdx.z;
    const int x0 = blockIdx.x * TW;
    const int y0 = blockIdx.y * STRIP;

    const float* __restrict__ p1 = img1 + (size_t)plane * (IMG_W * IMG_H);
    const float* __restrict__ p2 = img2 + (size_t)plane * (IMG_W * IMG_H);

    const int gx = x0 - 5 + tx;
    const bool xok = (gx >= 0) && (gx < IMG_W);
    const int xlim = (IMG_W - x0 < TW) ? (IMG_W - x0) : TW;

    unsigned ring[8][4];   // vertical accumulators; slot = pair mod 8 (persists across chunks)
    float lsum = 0.f;

    // ---------- prologue: stream rows 0..10 (y = y0-5 .. y0+5), no stores ----------
#pragma unroll
    for (int s = 0; s < 11; s++) {
        float a, b;
        load_centered(p1, p2, y0 - 5 + s, gx, xok, a, b);
        unsigned pq[4];
        make_pq(a, b, pq);
#pragma unroll
        for (int qp = 0; qp <= 5; qp++) {
            const int k = s - 2 * qp;          // compile-time
            if (k >= 0) {
#pragma unroll
                for (int q = 0; q < 4; q++) {
                    if (k == 0) ring[qp][q] = hmul2u(pq[q], wk2(0));
                    else        ring[qp][q] = hfma2u(pq[q], wk2(k), ring[qp][q]);
                }
            }
        }
    }

    // ---------- chunk pipeline: B(c) -> sync -> C(c) ----------
    for (int c = 0; c < CHUNKS; c++) {
        unsigned* buf = vw + (c & 1) * BUFWORDS;
        const int gyc = y0 + 6 + 16 * c;

        // Phase B: 16 input rows; pair q' completes at even s (slot s/2)
#pragma unroll
        for (int s = 0; s < 16; s++) {
            float a, b;
            load_centered(p1, p2, gyc + s, gx, xok, a, b);
            unsigned pq[4];
            make_pq(a, b, pq);
#pragma unroll
            for (int qp = 0; qp <= 13; qp++) {
                const int k = 11 + s - 2 * qp;   // compile-time
                if (k >= 0 && k <= 11) {
                    const int sl = qp & 7;
#pragma unroll
                    for (int q = 0; q < 4; q++) {
                        if (k == 0) ring[sl][q] = hmul2u(pq[q], wk2(0));
                        else        ring[sl][q] = hfma2u(pq[q], wk2(k), ring[sl][q]);
                    }
                }
            }
            if ((s & 1) == 0) {
                const int sl = s >> 1;
                uint4 w4 = make_uint4(ring[sl][0], ring[sl][1], ring[sl][2], ring[sl][3]);
                *reinterpret_cast<uint4*>(buf + sl * PITCH + tx * 4) = w4;
            }
        }
        __syncthreads();

        // Phase C: horizontal blur + epilogue; two 4-wide windows per thread
        const int rp  = tx & 7;       // pair-row (output rows 16c+2rp, +1)
        const int seg = tx >> 3;      // 0..23
#pragma unroll
        for (int win = 0; win < 2; win++) {
            const int c0 = seg * 8 + win * 4;
            const unsigned* rowp = buf + rp * PITCH + c0 * 4;
            unsigned acc[4][4];
#pragma unroll
            for (int i = 0; i < 14; i++) {
                // LDS.128: 4 quantities x 2 rows of column c0+i; tail overreads
                // stay inside the padded allocation, feed only discarded outputs.
                const uint4 w4 = *reinterpret_cast<const uint4*>(rowp + i * 4);
                unsigned pv[4] = {w4.x, w4.y, w4.z, w4.w};
#pragma unroll
                for (int xo = 0; xo < 4; xo++) {
                    const int k = i - xo;
                    if (k >= 0 && k <= 10) {
#pragma unroll
                        for (int q = 0; q < 4; q++) {
                            if (k == 0) acc[xo][q] = hmul2u(pv[q], wb2(0));
                            else        acc[xo][q] = hfma2u(pv[q], wb2(k < 6 ? k : 10 - k), acc[xo][q]);
                        }
                    }
                }
            }
#pragma unroll
            for (int xo = 0; xo < 4; xo++) {
                const int xout = c0 + xo;
                if (xout < xlim) {
                    const float2 mu1c = unpack_h2(acc[xo][0]);
                    const float2 mu2c = unpack_h2(acc[xo][1]);
                    const float2 eppc = unpack_h2(acc[xo][2]);
                    const float2 e12c = unpack_h2(acc[xo][3]);
#pragma unroll
                    for (int h = 0; h < 2; h++) {
                        const float m1c = h ? mu1c.y : mu1c.x;
                        const float m2c = h ? mu2c.y : mu2c.x;
                        const float epc = h ? eppc.y : eppc.x;
                        const float exc = h ? e12c.y : e12c.x;
                        const float ssum = epc - fmaf(m1c, m1c, m2c * m2c); // s1+s2
                        const float s12  = exc - m1c * m2c;
                        const float m1 = m1c + 0.5f;
                        const float m2 = m2c + 0.5f;
                        const float msum = fmaf(m1, m1, m2 * m2);
                        const float m12  = m1 * m2;
                        const float num = fmaf(2.f, m12, C1V) * fmaf(2.f, s12, C2V);
                        const float den = (msum + C1V) * (ssum + C2V);
                        lsum += __fdividef(num, den);
                    }
                }
            }
        }
    }

    // ---------- reduction: shuffle -> smem -> one atomic per block ----------
#pragma unroll
    for (int off = 16; off > 0; off >>= 1)
        lsum += __shfl_xor_sync(0xffffffffu, lsum, off);
    if ((tx & 31) == 0) red[tx >> 5] = lsum;
    __syncthreads();

    if (tx == 0) {
        float bsum = 0.f;
#pragma unroll
        for (int w = 0; w < NTHREADS / 32; w++) bsum += red[w];
        atomicAdd(&g_accum, bsum);
        __threadfence();
        const unsigned int old = atomicAdd(&g_count, 1u);
        if (old == NBLOCKS - 1) {
            __threadfence();
            const float total = *(volatile float*)&g_accum;
            out[0] = 1.0f - total * (1.0f / NPIX);
            *(volatile float*)&g_accum = 0.f;
            *(volatile unsigned int*)&g_count = 0u;
        }
    }
}

extern "C" void kernel_launch(void* const* d_in, const int* in_sizes, int n_in,
                              void* d_out, int out_size) {
    const float* img1 = (const float*)d_in[0];
    const float* img2 = (const float*)d_in[1];

    const int smem = SMEM_WORDS * (int)sizeof(unsigned);   // 50,048 B
    cudaFuncSetAttribute(ssim_main, cudaFuncAttributeMaxDynamicSharedMemorySize, smem);

    dim3 grid((IMG_W + TW - 1) / TW, IMG_H / STRIP, PLANES);  // (3, 2, 96)
    ssim_main<<<grid, NTHREADS, smem>>>(img1, img2, (float*)d_out);
}

// round 13
// speedup vs baseline: 1.2816x; 1.2816x over previous
#include <cuda_runtime.h>
#include <cuda_fp16.h>

#define RW 192
#define TW 182
#define TH 16          // output rows per tile
#define NP 8           // row pairs per tile
#define RH 26          // TH + 10 input rows
#define PITCH 772      // u32 words per pair-row: 192*4 + 4; 772%32==4 -> conflict-free
#define SMEM_WORDS (NP * PITCH + 160)   // pad covers phase-C tail overreads
#define NTHREADS 192
#define IMG_W 512
#define IMG_H 512
#define PLANES 96
#define NBLOCKS (3 * 32 * 96)
#define NPIX 25165824.0f

static constexpr float C1V = 0.0001f;
static constexpr float C2V = 0.0009f;

__host__ __device__ constexpr float wt(int k) {
    return (k == 0 || k == 10) ? 0.00102838f
         : (k == 1 || k == 9)  ? 0.00759876f
         : (k == 2 || k == 8)  ? 0.03600077f
         : (k == 3 || k == 7)  ? 0.10936069f
         : (k == 4 || k == 6)  ? 0.21300553f
         : (k == 5)            ? 0.26601172f
         : 0.0f;
}

__device__ float g_accum;
__device__ unsigned int g_count;

// ---- raw half2 helpers on u32 ----
__device__ __forceinline__ unsigned hfma2u(unsigned a, unsigned b, unsigned c) {
    unsigned d; asm("fma.rn.f16x2 %0,%1,%2,%3;" : "=r"(d) : "r"(a), "r"(b), "r"(c)); return d;
}
__device__ __forceinline__ unsigned hmul2u(unsigned a, unsigned b) {
    unsigned d; asm("mul.rn.f16x2 %0,%1,%2;" : "=r"(d) : "r"(a), "r"(b)); return d;
}
__device__ __forceinline__ unsigned hsub2u(unsigned a, unsigned b) {
    unsigned d; asm("sub.rn.f16x2 %0,%1,%2;" : "=r"(d) : "r"(a), "r"(b)); return d;
}
__device__ __forceinline__ unsigned pack_h2(float lo, float hi) {
    unsigned d;
    asm("{\n\t.reg .b16 l, h;\n\t"
        "cvt.rn.f16.f32 l, %1;\n\t"
        "cvt.rn.f16.f32 h, %2;\n\t"
        "mov.b32 %0, {l, h};\n\t}"
        : "=r"(d) : "f"(lo), "f"(hi));
    return d;
}
__device__ __forceinline__ unsigned bcast_h2(float f) {
    unsigned d; asm("cvt.rn.f16x2.f32 %0, %1, %1;" : "=r"(d) : "f"(f)); return d;
}
__device__ __forceinline__ float2 unpack_h2(unsigned u) {
    __half2 h = *reinterpret_cast<__half2*>(&u);
    return make_float2(__low2float(h), __high2float(h));
}

// Vertical blur on CENTERED inputs (ac = a-0.5; out-of-image -> -0.5).
// fp16 moments: s = ah^2+bh^2, m = ah*bh (validated: rel_err unchanged).
// Lanes of each half2 = output rows (2p, 2p+1). Weight pair (w[k], w[k-1]).
template <bool YSAFE, bool XSAFE>
__device__ __forceinline__ void vblur(const float* __restrict__ p1,
                                      const float* __restrict__ p2,
                                      unsigned* __restrict__ vw,
                                      int y0, int gx, bool xok, int tx,
                                      const unsigned (&WK)[12]) {
    unsigned acc[6][4];   // ring of 6 live pairs x 4 quantities

#pragma unroll
    for (int r = 0; r < RH; r++) {
        const int gy = y0 - 5 + r;
        float a, b;
        if (YSAFE && XSAFE) {
            const int idx = gy * IMG_W + gx;
            a = __ldg(p1 + idx) - 0.5f;
            b = __ldg(p2 + idx) - 0.5f;
        } else {
            a = -0.5f; b = -0.5f;
            const bool ok = (XSAFE || xok) && (YSAFE || ((gy >= 0) && (gy < IMG_H)));
            if (ok) {
                const int idx = gy * IMG_W + gx;
                a = __ldg(p1 + idx) - 0.5f;
                b = __ldg(p2 + idx) - 0.5f;
            }
        }
        unsigned pq[4];
        pq[0] = bcast_h2(a);
        pq[1] = bcast_h2(b);
        pq[2] = hfma2u(pq[0], pq[0], hmul2u(pq[1], pq[1]));  // ac^2+bc^2
        pq[3] = hmul2u(pq[0], pq[1]);                        // ac*bc

#pragma unroll
        for (int p = 0; p < NP; p++) {
            const int k = r - 2 * p;            // compile-time after unroll
            if (k >= 0 && k <= 11) {
                const int j = p % 6;
                if (k == 0) {
#pragma unroll
                    for (int q = 0; q < 4; q++)
                        acc[j][q] = hmul2u(pq[q], WK[0]);   // fresh pair (lane1 *0)
                } else {
#pragma unroll
                    for (int q = 0; q < 4; q++)
                        acc[j][q] = hfma2u(pq[q], WK[k], acc[j][q]);
                }
            }
        }
        if (r >= 11 && ((r - 11) & 1) == 0) {
            const int p = (r - 11) >> 1;
            const int j = p % 6;
            uint4 w4 = make_uint4(acc[j][0], acc[j][1], acc[j][2], acc[j][3]);
            *reinterpret_cast<uint4*>(vw + p * PITCH + tx * 4) = w4;
        }
    }
}

__global__ void __launch_bounds__(NTHREADS, 5)
ssim_main(const float* __restrict__ img1, const float* __restrict__ img2,
          float* __restrict__ out) {
    extern __shared__ unsigned vw[];      // [NP][PITCH] + pad
    __shared__ float red[NTHREADS / 32];

    const int tx = threadIdx.x;
    const int plane = blockIdx.z;
    const int x0 = blockIdx.x * TW;
    const int y0 = blockIdx.y * TH;

    const float* __restrict__ p1 = img1 + (size_t)plane * (IMG_W * IMG_H);
    const float* __restrict__ p2 = img2 + (size_t)plane * (IMG_W * IMG_H);

    const int gx = x0 - 5 + tx;
    const bool xok = (gx >= 0) && (gx < IMG_W);

    unsigned WK[12];
#pragma unroll
    for (int k = 0; k < 12; k++)
        WK[k] = pack_h2(wt(k), wt(k - 1));

    // ---------- Phase B (Y/X-safe specialization) ----------
    const bool ysafe = (y0 >= 5) && (y0 + TH + 5 <= IMG_H);
    const bool xsafe = (blockIdx.x == 1);       // gx in [177,368] -> always in range
    if (ysafe) {
        if (xsafe) vblur<true , true >(p1, p2, vw, y0, gx, xok, tx, WK);
        else       vblur<true , false>(p1, p2, vw, y0, gx, xok, tx, WK);
    } else {
        if (xsafe) vblur<false, true >(p1, p2, vw, y0, gx, xok, tx, WK);
        else       vblur<false, false>(p1, p2, vw, y0, gx, xok, tx, WK);
    }
    __syncthreads();

    // ---------- Phase C: horizontal blur + SSIM epilogue ----------
    const int rp  = tx & 7;       // pair-row 0..7 (output rows 2rp, 2rp+1)
    const int seg = tx >> 3;      // 0..23, each covers 8 output columns
    const int c0  = seg * 8;
    const int xlim = (IMG_W - x0 < TW) ? (IMG_W - x0) : TW;

    unsigned WB[6];               // broadcast weights (symmetric)
#pragma unroll
    for (int k = 0; k < 6; k++) WB[k] = bcast_h2(wt(k));

    unsigned acc[8][4];
    const unsigned* rowp = vw + rp * PITCH + c0 * 4;

#pragma unroll
    for (int i = 0; i < 18; i++) {
        // One LDS.128: 4 quantities x 2 rows of column c0+i. Tail overreads
        // stay inside the padded allocation and feed only discarded outputs.
        const uint4 w4 = *reinterpret_cast<const uint4*>(rowp + i * 4);
        unsigned pv[4] = {w4.x, w4.y, w4.z, w4.w};
#pragma unroll
        for (int xo = 0; xo < 8; xo++) {
            const int k = i - xo;
            if (k >= 0 && k <= 10) {
                const int wi = (k < 6) ? k : (10 - k);
                if (k == 0) {
#pragma unroll
                    for (int q = 0; q < 4; q++)
                        acc[xo][q] = hmul2u(pv[q], WB[0]);
                } else {
#pragma unroll
                    for (int q = 0; q < 4; q++)
                        acc[xo][q] = hfma2u(pv[q], WB[wi], acc[xo][q]);
                }
            }
        }
    }

    float lsum = 0.f;
#pragma unroll
    for (int xo = 0; xo < 8; xo++) {
        const int xout = c0 + xo;
        if (xout < xlim) {
            // contrast terms in h2 (operands already fp16-quantized; the
            // extra rounding is second-order)
            const unsigned msumc_h2 = hfma2u(acc[xo][0], acc[xo][0],
                                             hmul2u(acc[xo][1], acc[xo][1]));
            const unsigned ssum_h2  = hsub2u(acc[xo][2], msumc_h2);
            const unsigned s12_h2   = hsub2u(acc[xo][3],
                                             hmul2u(acc[xo][0], acc[xo][1]));
            const float2 mu1c = unpack_h2(acc[xo][0]);
            const float2 mu2c = unpack_h2(acc[xo][1]);
            const float2 ssm2 = unpack_h2(ssum_h2);
            const float2 s122 = unpack_h2(s12_h2);
#pragma unroll
            for (int h = 0; h < 2; h++) {
                const float m1c  = h ? mu1c.y : mu1c.x;
                const float m2c  = h ? mu2c.y : mu2c.x;
                const float ssum = h ? ssm2.y : ssm2.x;
                const float s12  = h ? s122.y : s122.x;
                const float m1 = m1c + 0.5f;
                const float m2 = m2c + 0.5f;
                const float msum = fmaf(m1, m1, m2 * m2);
                const float m12  = m1 * m2;
                const float num = fmaf(2.f, m12, C1V) * fmaf(2.f, s12, C2V);
                const float den = (msum + C1V) * (ssum + C2V);
                lsum += __fdividef(num, den);
            }
        }
    }

    // ---------- reduction: shuffle -> smem -> one atomic per block ----------
#pragma unroll
    for (int off = 16; off > 0; off >>= 1)
        lsum += __shfl_xor_sync(0xffffffffu, lsum, off);
    if ((tx & 31) == 0) red[tx >> 5] = lsum;
    __syncthreads();

    if (tx == 0) {
        float bsum = 0.f;
#pragma unroll
        for (int w = 0; w < NTHREADS / 32; w++) bsum += red[w];
        atomicAdd(&g_accum, bsum);
        __threadfence();
        const unsigned int old = atomicAdd(&g_count, 1u);
        if (old == NBLOCKS - 1) {
            __threadfence();
            const float total = *(volatile float*)&g_accum;
            out[0] = 1.0f - total * (1.0f / NPIX);
            *(volatile float*)&g_accum = 0.f;
            *(volatile unsigned int*)&g_count = 0u;
        }
    }
}

extern "C" void kernel_launch(void* const* d_in, const int* in_sizes, int n_in,
                              void* d_out, int out_size) {
    const float* img1 = (const float*)d_in[0];
    const float* img2 = (const float*)d_in[1];

    const int smem = SMEM_WORDS * (int)sizeof(unsigned);   // 25,344 B
    cudaFuncSetAttribute(ssim_main, cudaFuncAttributeMaxDynamicSharedMemorySize, smem);

    dim3 grid((IMG_W + TW - 1) / TW, IMG_H / TH, PLANES);  // (3, 32, 96)
    ssim_main<<<grid, NTHREADS, smem>>>(img1, img2, (float*)d_out);
}

// round 14
// speedup vs baseline: 1.3353x; 1.0419x over previous
#include <cuda_runtime.h>
#include <cuda_fp16.h>

#define RW 192
#define TW 182
#define TH 16          // output rows per tile
#define NP 8           // row pairs per tile
#define RH 26          // TH + 10 input rows
#define PITCH 772      // u32 words per pair-row: 192*4 + 4; 772%32==4 -> conflict-free
#define SMEM_WORDS (NP * PITCH + 160)   // pad covers phase-C tail overreads
#define NTHREADS 192
#define IMG_W 512
#define IMG_H 512
#define PLANES 96
#define NBLOCKS (3 * 32 * 96)
#define NPIX 25165824.0f

static constexpr float C1V = 0.0001f;
static constexpr float C2V = 0.0009f;

// fp16 bit patterns of the Gaussian(sigma=1.5,k=11) weights (== cvt.rn.f16.f32,
// validated bit-exact in R12: identical rel_err to runtime cvt).
__host__ __device__ constexpr unsigned hw(int k) {
    return (k == 0 || k == 10) ? 0x1436u
         : (k == 1 || k == 9)  ? 0x1FC8u
         : (k == 2 || k == 8)  ? 0x289Cu
         : (k == 3 || k == 7)  ? 0x2F00u
         : (k == 4 || k == 6)  ? 0x32D1u
         : (k == 5)            ? 0x3442u
         : 0u;
}
// vertical weight pair (lo=w[k], hi=w[k-1]); horizontal broadcast
__host__ __device__ constexpr unsigned wk2(int k) { return hw(k) | (hw(k - 1) << 16); }
__host__ __device__ constexpr unsigned wb2(int k) { return hw(k) | (hw(k) << 16); }

__device__ float g_accum;
__device__ unsigned int g_count;

// ---- raw half2 helpers on u32 ----
__device__ __forceinline__ unsigned hfma2u(unsigned a, unsigned b, unsigned c) {
    unsigned d; asm("fma.rn.f16x2 %0,%1,%2,%3;" : "=r"(d) : "r"(a), "r"(b), "r"(c)); return d;
}
__device__ __forceinline__ unsigned hmul2u(unsigned a, unsigned b) {
    unsigned d; asm("mul.rn.f16x2 %0,%1,%2;" : "=r"(d) : "r"(a), "r"(b)); return d;
}
__device__ __forceinline__ unsigned hadd2u(unsigned a, unsigned b) {
    unsigned d; asm("add.rn.f16x2 %0,%1,%2;" : "=r"(d) : "r"(a), "r"(b)); return d;
}
__device__ __forceinline__ unsigned hsub2u(unsigned a, unsigned b) {
    unsigned d; asm("sub.rn.f16x2 %0,%1,%2;" : "=r"(d) : "r"(a), "r"(b)); return d;
}
__device__ __forceinline__ unsigned bcast_h2(float f) {
    unsigned d; asm("cvt.rn.f16x2.f32 %0, %1, %1;" : "=r"(d) : "f"(f)); return d;
}
__device__ __forceinline__ float2 unpack_h2(unsigned u) {
    __half2 h = *reinterpret_cast<__half2*>(&u);
    return make_float2(__low2float(h), __high2float(h));
}

// Vertical blur on CENTERED inputs (ac = a-0.5; out-of-image -> -0.5).
// fp16 moments; lanes of each half2 = output rows (2p, 2p+1).
template <bool YSAFE, bool XSAFE>
__device__ __forceinline__ void vblur(const float* __restrict__ p1,
                                      const float* __restrict__ p2,
                                      unsigned* __restrict__ vw,
                                      int y0, int gx, bool xok, int tx) {
    unsigned acc[6][4];   // ring of 6 live pairs x 4 quantities

#pragma unroll
    for (int r = 0; r < RH; r++) {
        const int gy = y0 - 5 + r;
        float a, b;
        if (YSAFE && XSAFE) {
            const int idx = gy * IMG_W + gx;
            a = __ldg(p1 + idx) - 0.5f;
            b = __ldg(p2 + idx) - 0.5f;
        } else {
            a = -0.5f; b = -0.5f;
            const bool ok = (XSAFE || xok) && (YSAFE || ((gy >= 0) && (gy < IMG_H)));
            if (ok) {
                const int idx = gy * IMG_W + gx;
                a = __ldg(p1 + idx) - 0.5f;
                b = __ldg(p2 + idx) - 0.5f;
            }
        }
        unsigned pq[4];
        pq[0] = bcast_h2(a);
        pq[1] = bcast_h2(b);
        pq[2] = hfma2u(pq[0], pq[0], hmul2u(pq[1], pq[1]));  // ac^2+bc^2
        pq[3] = hmul2u(pq[0], pq[1]);                        // ac*bc

#pragma unroll
        for (int p = 0; p < NP; p++) {
            const int k = r - 2 * p;            // compile-time after unroll
            if (k >= 0 && k <= 11) {
                const int j = p % 6;
                if (k == 0) {
#pragma unroll
                    for (int q = 0; q < 4; q++)
                        acc[j][q] = hmul2u(pq[q], wk2(0));   // fresh pair (lane1 *0)
                } else {
#pragma unroll
                    for (int q = 0; q < 4; q++)
                        acc[j][q] = hfma2u(pq[q], wk2(k), acc[j][q]);
                }
            }
        }
        if (r >= 11 && ((r - 11) & 1) == 0) {
            const int p = (r - 11) >> 1;
            const int j = p % 6;
            uint4 w4 = make_uint4(acc[j][0], acc[j][1], acc[j][2], acc[j][3]);
            *reinterpret_cast<uint4*>(vw + p * PITCH + tx * 4) = w4;
        }
    }
}

__global__ void __launch_bounds__(NTHREADS, 6)
ssim_main(const float* __restrict__ img1, const float* __restrict__ img2,
          float* __restrict__ out) {
    extern __shared__ unsigned vw[];      // [NP][PITCH] + pad
    __shared__ float red[NTHREADS / 32];

    const int tx = threadIdx.x;
    const int plane = blockIdx.z;
    const int x0 = blockIdx.x * TW;
    const int y0 = blockIdx.y * TH;

    const float* __restrict__ p1 = img1 + (size_t)plane * (IMG_W * IMG_H);
    const float* __restrict__ p2 = img2 + (size_t)plane * (IMG_W * IMG_H);

    const int gx = x0 - 5 + tx;
    const bool xok = (gx >= 0) && (gx < IMG_W);

    // ---------- Phase B (Y/X-safe specialization) ----------
    const bool ysafe = (y0 >= 5) && (y0 + TH + 5 <= IMG_H);
    const bool xsafe = (blockIdx.x == 1);       // gx in [177,368] -> always in range
    if (ysafe) {
        if (xsafe) vblur<true , true >(p1, p2, vw, y0, gx, xok, tx);
        else       vblur<true , false>(p1, p2, vw, y0, gx, xok, tx);
    } else {
        if (xsafe) vblur<false, true >(p1, p2, vw, y0, gx, xok, tx);
        else       vblur<false, false>(p1, p2, vw, y0, gx, xok, tx);
    }
    __syncthreads();

    // ---------- Phase C: horizontal blur + SSIM epilogue ----------
    const int rp  = tx & 7;       // pair-row 0..7 (output rows 2rp, 2rp+1)
    const int seg = tx >> 3;      // 0..23, each covers 8 output columns
    const int c0  = seg * 8;
    const int xlim = (IMG_W - x0 < TW) ? (IMG_W - x0) : TW;

    unsigned acc[8][4];
    const unsigned* rowp = vw + rp * PITCH + c0 * 4;

#pragma unroll
    for (int i = 0; i < 18; i++) {
        // One LDS.128: 4 quantities x 2 rows of column c0+i. Tail overreads
        // stay inside the padded allocation and feed only discarded outputs.
        const uint4 w4 = *reinterpret_cast<const uint4*>(rowp + i * 4);
        unsigned pv[4] = {w4.x, w4.y, w4.z, w4.w};
#pragma unroll
        for (int xo = 0; xo < 8; xo++) {
            const int k = i - xo;
            if (k >= 0 && k <= 10) {
                if (k == 0) {
#pragma unroll
                    for (int q = 0; q < 4; q++)
                        acc[xo][q] = hmul2u(pv[q], wb2(0));
                } else {
#pragma unroll
                    for (int q = 0; q < 4; q++)
                        acc[xo][q] = hfma2u(pv[q], wb2(k < 6 ? k : 10 - k), acc[xo][q]);
                }
            }
        }
    }

    // h2 constants for the pair-packed epilogue
    const unsigned HC1   = bcast_h2(C1V);
    const unsigned HC2   = bcast_h2(C2V);
    const unsigned HTWO  = bcast_h2(2.0f);
    const unsigned HHALF = bcast_h2(0.5f);
    const unsigned HQTR  = bcast_h2(0.25f);
    const unsigned HHC1  = bcast_h2(0.5f + C1V);

    float lsum = 0.f;
#pragma unroll
    for (int xo = 0; xo < 8; xo++) {
        const int xout = c0 + xo;
        if (xout < xlim) {
            const unsigned mu1c = acc[xo][0];
            const unsigned mu2c = acc[xo][1];
            const unsigned epc  = acc[xo][2];
            const unsigned exc  = acc[xo][3];
            // centered second moments
            const unsigned msumc = hfma2u(mu1c, mu1c, hmul2u(mu2c, mu2c));
            const unsigned ssum  = hsub2u(epc, msumc);               // s1+s2
            const unsigned m12c  = hmul2u(mu1c, mu2c);
            const unsigned s12   = hsub2u(exc, m12c);
            // de-center: u = mu1c+mu2c; m12 = m12c + u/2 + 1/4;
            //            msum+C1 = msumc + u + (1/2+C1)
            const unsigned u      = hadd2u(mu1c, mu2c);
            const unsigned m12    = hadd2u(m12c, hfma2u(u, HHALF, HQTR));
            const unsigned msumC1 = hadd2u(msumc, hadd2u(u, HHC1));
            // numerator/denominator factors
            const unsigned numf1  = hfma2u(m12, HTWO, HC1);
            const unsigned numf2  = hfma2u(s12, HTWO, HC2);
            const unsigned num_h  = hmul2u(numf1, numf2);
            const unsigned ssumC2 = hadd2u(ssum, HC2);
            const unsigned den_h  = hmul2u(msumC1, ssumC2);
            const float2 numf = unpack_h2(num_h);
            const float2 denf = unpack_h2(den_h);
            lsum += __fdividef(numf.x, denf.x);
            lsum += __fdividef(numf.y, denf.y);
        }
    }

    // ---------- reduction: shuffle -> smem -> one atomic per block ----------
#pragma unroll
    for (int off = 16; off > 0; off >>= 1)
        lsum += __shfl_xor_sync(0xffffffffu, lsum, off);
    if ((tx & 31) == 0) red[tx >> 5] = lsum;
    __syncthreads();

    if (tx == 0) {
        float bsum = 0.f;
#pragma unroll
        for (int w = 0; w < NTHREADS / 32; w++) bsum += red[w];
        atomicAdd(&g_accum, bsum);
        __threadfence();
        const unsigned int old = atomicAdd(&g_count, 1u);
        if (old == NBLOCKS - 1) {
            __threadfence();
            const float total = *(volatile float*)&g_accum;
            out[0] = 1.0f - total * (1.0f / NPIX);
            *(volatile float*)&g_accum = 0.f;
            *(volatile unsigned int*)&g_count = 0u;
        }
    }
}

extern "C" void kernel_launch(void* const* d_in, const int* in_sizes, int n_in,
                              void* d_out, int out_size) {
    const float* img1 = (const float*)d_in[0];
    const float* img2 = (const float*)d_in[1];

    const int smem = SMEM_WORDS * (int)sizeof(unsigned);   // 25,344 B
    cudaFuncSetAttribute(ssim_main, cudaFuncAttributeMaxDynamicSharedMemorySize, smem);

    dim3 grid((IMG_W + TW - 1) / TW, IMG_H / TH, PLANES);  // (3, 32, 96)
    ssim_main<<<grid, NTHREADS, smem>>>(img1, img2, (float*)d_out);
}

// round 15
// speedup vs baseline: 1.3380x; 1.0021x over previous
#include <cuda_runtime.h>
#include <cuda_fp16.h>

#define RW 192
#define TW 182
#define TH 16          // output rows per tile
#define NP 8           // row pairs per tile
#define RH 26          // TH + 10 input rows
#define PITCH 772      // u32 words per pair-row: 192*4 + 4; 772%32==4 -> conflict-free
#define SMEM_WORDS (NP * PITCH + 160)   // pad covers phase-C tail overreads
#define NTHREADS 192
#define IMG_W 512
#define IMG_H 512
#define PLANES 96
#define NBLOCKS (3 * 32 * 96)
#define NPIX 25165824.0f

static constexpr float C1V = 0.0001f;
static constexpr float C2V = 0.0009f;

// fp16 bit patterns of the Gaussian(sigma=1.5,k=11) weights (== cvt.rn.f16.f32,
// validated bit-exact in R12).
__host__ __device__ constexpr unsigned hw(int k) {
    return (k == 0 || k == 10) ? 0x1436u
         : (k == 1 || k == 9)  ? 0x1FC8u
         : (k == 2 || k == 8)  ? 0x289Cu
         : (k == 3 || k == 7)  ? 0x2F00u
         : (k == 4 || k == 6)  ? 0x32D1u
         : (k == 5)            ? 0x3442u
         : 0u;
}
__host__ __device__ constexpr unsigned wk2(int k) { return hw(k) | (hw(k - 1) << 16); }
__host__ __device__ constexpr unsigned wb2(int k) { return hw(k) | (hw(k) << 16); }

__device__ float g_accum;
__device__ unsigned int g_count;

__device__ __forceinline__ unsigned hfma2u(unsigned a, unsigned b, unsigned c) {
    unsigned d; asm("fma.rn.f16x2 %0,%1,%2,%3;" : "=r"(d) : "r"(a), "r"(b), "r"(c)); return d;
}
__device__ __forceinline__ unsigned hmul2u(unsigned a, unsigned b) {
    unsigned d; asm("mul.rn.f16x2 %0,%1,%2;" : "=r"(d) : "r"(a), "r"(b)); return d;
}
__device__ __forceinline__ unsigned hadd2u(unsigned a, unsigned b) {
    unsigned d; asm("add.rn.f16x2 %0,%1,%2;" : "=r"(d) : "r"(a), "r"(b)); return d;
}
__device__ __forceinline__ unsigned hsub2u(unsigned a, unsigned b) {
    unsigned d; asm("sub.rn.f16x2 %0,%1,%2;" : "=r"(d) : "r"(a), "r"(b)); return d;
}
__device__ __forceinline__ unsigned bcast_h2(float f) {
    unsigned d; asm("cvt.rn.f16x2.f32 %0, %1, %1;" : "=r"(d) : "f"(f)); return d;
}
__device__ __forceinline__ float2 unpack_h2(unsigned u) {
    __half2 h = *reinterpret_cast<__half2*>(&u);
    return make_float2(__low2float(h), __high2float(h));
}

// Vertical blur on CENTERED inputs (ac = a-0.5; out-of-image -> -0.5).
// fp16 moments; lanes of each half2 = output rows (2p, 2p+1).
template <bool YSAFE, bool XSAFE>
__device__ __forceinline__ void vblur(const float* __restrict__ p1,
                                      const float* __restrict__ p2,
                                      unsigned* __restrict__ vw,
                                      int y0, int gx, bool xok, int tx) {
    unsigned acc[6][4];   // ring of 6 live pairs x 4 quantities

#pragma unroll
    for (int r = 0; r < RH; r++) {
        const int gy = y0 - 5 + r;
        float a, b;
        if (YSAFE && XSAFE) {
            const int idx = gy * IMG_W + gx;
            a = __ldg(p1 + idx) - 0.5f;
            b = __ldg(p2 + idx) - 0.5f;
        } else {
            a = -0.5f; b = -0.5f;
            const bool ok = (XSAFE || xok) && (YSAFE || ((gy >= 0) && (gy < IMG_H)));
            if (ok) {
                const int idx = gy * IMG_W + gx;
                a = __ldg(p1 + idx) - 0.5f;
                b = __ldg(p2 + idx) - 0.5f;
            }
        }
        unsigned pq[4];
        pq[0] = bcast_h2(a);
        pq[1] = bcast_h2(b);
        pq[2] = hfma2u(pq[0], pq[0], hmul2u(pq[1], pq[1]));  // ac^2+bc^2
        pq[3] = hmul2u(pq[0], pq[1]);                        // ac*bc

#pragma unroll
        for (int p = 0; p < NP; p++) {
            const int k = r - 2 * p;            // compile-time after unroll
            if (k >= 0 && k <= 11) {
                const int j = p % 6;
                if (k == 0) {
#pragma unroll
                    for (int q = 0; q < 4; q++)
                        acc[j][q] = hmul2u(pq[q], wk2(0));   // fresh pair (lane1 *0)
                } else {
#pragma unroll
                    for (int q = 0; q < 4; q++)
                        acc[j][q] = hfma2u(pq[q], wk2(k), acc[j][q]);
                }
            }
        }
        if (r >= 11 && ((r - 11) & 1) == 0) {
            const int p = (r - 11) >> 1;
            const int j = p % 6;
            uint4 w4 = make_uint4(acc[j][0], acc[j][1], acc[j][2], acc[j][3]);
            *reinterpret_cast<uint4*>(vw + p * PITCH + tx * 4) = w4;
        }
    }
}

__global__ void __launch_bounds__(NTHREADS, 6)
ssim_main(const float* __restrict__ img1, const float* __restrict__ img2,
          float* __restrict__ out) {
    extern __shared__ unsigned vw[];      // [NP][PITCH] + pad
    __shared__ float red[NTHREADS / 32];

    const int tx = threadIdx.x;
    const int plane = blockIdx.z;
    const int x0 = blockIdx.x * TW;
    const int y0 = blockIdx.y * TH;

    const float* __restrict__ p1 = img1 + (size_t)plane * (IMG_W * IMG_H);
    const float* __restrict__ p2 = img2 + (size_t)plane * (IMG_W * IMG_H);

    const int gx = x0 - 5 + tx;
    const bool xok = (gx >= 0) && (gx < IMG_W);
    const int xlim = (IMG_W - x0 < TW) ? (IMG_W - x0) : TW;

    // Dead-column skip (warp-uniform on edge blocks): a raw column tx is
    // needed only if some KEPT output xo (xo < xlim) taps it: tx <= xlim+9.
    const bool bcol_live = (tx <= xlim + 9);

    // ---------- Phase B (Y/X-safe specialization; dead warps skip) ----------
    if (bcol_live) {
        const bool ysafe = (y0 >= 5) && (y0 + TH + 5 <= IMG_H);
        const bool xsafe = (blockIdx.x == 1);   // gx in [177,368] -> always in range
        if (ysafe) {
            if (xsafe) vblur<true , true >(p1, p2, vw, y0, gx, xok, tx);
            else       vblur<true , false>(p1, p2, vw, y0, gx, xok, tx);
        } else {
            if (xsafe) vblur<false, true >(p1, p2, vw, y0, gx, xok, tx);
            else       vblur<false, false>(p1, p2, vw, y0, gx, xok, tx);
        }
    }
    __syncthreads();

    // ---------- Phase C: horizontal blur + SSIM epilogue ----------
    const int rp  = tx & 7;       // pair-row 0..7 (output rows 2rp, 2rp+1)
    const int seg = tx >> 3;      // 0..23, each covers 8 output columns
    const int c0  = seg * 8;

    float lsum = 0.f;

    if (c0 < xlim) {              // dead segments (incl. seg 23 everywhere,
                                  // segs 19-23 on edge blocks) skip entirely
        unsigned acc[8][4];
        const unsigned* rowp = vw + rp * PITCH + c0 * 4;

#pragma unroll
        for (int i = 0; i < 18; i++) {
            // One LDS.128: 4 quantities x 2 rows of column c0+i. Tail overreads
            // stay inside the padded allocation / un-refreshed smem and feed
            // only outputs discarded by the xout < xlim guard below.
            const uint4 w4 = *reinterpret_cast<const uint4*>(rowp + i * 4);
            unsigned pv[4] = {w4.x, w4.y, w4.z, w4.w};
#pragma unroll
            for (int xo = 0; xo < 8; xo++) {
                const int k = i - xo;
                if (k >= 0 && k <= 10) {
                    if (k == 0) {
#pragma unroll
                        for (int q = 0; q < 4; q++)
                            acc[xo][q] = hmul2u(pv[q], wb2(0));
                    } else {
#pragma unroll
                        for (int q = 0; q < 4; q++)
                            acc[xo][q] = hfma2u(pv[q], wb2(k < 6 ? k : 10 - k), acc[xo][q]);
                    }
                }
            }
        }

        // h2 constants for the pair-packed epilogue
        const unsigned HC1   = bcast_h2(C1V);
        const unsigned HC2   = bcast_h2(C2V);
        const unsigned HTWO  = bcast_h2(2.0f);
        const unsigned HHALF = bcast_h2(0.5f);
        const unsigned HQTR  = bcast_h2(0.25f);
        const unsigned HHC1  = bcast_h2(0.5f + C1V);

#pragma unroll
        for (int xo = 0; xo < 8; xo++) {
            const int xout = c0 + xo;
            if (xout < xlim) {
                const unsigned mu1c = acc[xo][0];
                const unsigned mu2c = acc[xo][1];
                const unsigned epc  = acc[xo][2];
                const unsigned exc  = acc[xo][3];
                const unsigned msumc = hfma2u(mu1c, mu1c, hmul2u(mu2c, mu2c));
                const unsigned ssum  = hsub2u(epc, msumc);            // s1+s2
                const unsigned m12c  = hmul2u(mu1c, mu2c);
                const unsigned s12   = hsub2u(exc, m12c);
                // de-center: u = mu1c+mu2c; m12 = m12c + u/2 + 1/4;
                //            msum+C1 = msumc + u + (1/2+C1)
                const unsigned u      = hadd2u(mu1c, mu2c);
                const unsigned m12    = hadd2u(m12c, hfma2u(u, HHALF, HQTR));
                const unsigned msumC1 = hadd2u(msumc, hadd2u(u, HHC1));
                const unsigned numf1  = hfma2u(m12, HTWO, HC1);
                const unsigned numf2  = hfma2u(s12, HTWO, HC2);
                const unsigned num_h  = hmul2u(numf1, numf2);
                const unsigned ssumC2 = hadd2u(ssum, HC2);
                const unsigned den_h  = hmul2u(msumC1, ssumC2);
                const float2 numf = unpack_h2(num_h);
                const float2 denf = unpack_h2(den_h);
                lsum += __fdividef(numf.x, denf.x);
                lsum += __fdividef(numf.y, denf.y);
            }
        }
    }

    // ---------- reduction: shuffle -> smem -> one atomic per block ----------
#pragma unroll
    for (int off = 16; off > 0; off >>= 1)
        lsum += __shfl_xor_sync(0xffffffffu, lsum, off);
    if ((tx & 31) == 0) red[tx >> 5] = lsum;
    __syncthreads();

    if (tx == 0) {
        float bsum = 0.f;
#pragma unroll
        for (int w = 0; w < NTHREADS / 32; w++) bsum += red[w];
        atomicAdd(&g_accum, bsum);
        __threadfence();
        const unsigned int old = atomicAdd(&g_count, 1u);
        if (old == NBLOCKS - 1) {
            __threadfence();
            const float total = *(volatile float*)&g_accum;
            out[0] = 1.0f - total * (1.0f / NPIX);
            *(volatile float*)&g_accum = 0.f;
            *(volatile unsigned int*)&g_count = 0u;
        }
    }
}

extern "C" void kernel_launch(void* const* d_in, const int* in_sizes, int n_in,
                              void* d_out, int out_size) {
    const float* img1 = (const float*)d_in[0];
    const float* img2 = (const float*)d_in[1];

    const int smem = SMEM_WORDS * (int)sizeof(unsigned);   // 25,344 B
    cudaFuncSetAttribute(ssim_main, cudaFuncAttributeMaxDynamicSharedMemorySize, smem);

    dim3 grid((IMG_W + TW - 1) / TW, IMG_H / TH, PLANES);  // (3, 32, 96)
    ssim_main<<<grid, NTHREADS, smem>>>(img1, img2, (float*)d_out);
}